// round 8
// baseline (speedup 1.0000x reference)
#include <cuda_runtime.h>
#include <cuda_bf16.h>
#include <cstdint>

// Problem constants
#define Bt 2
#define Tt 2048
#define Cc 1024
#define Hh 16
#define Dd 64
#define N3 (3 * Cc)          // 3072
#define Mm (Bt * Tt)         // 4096
#define ATT_SCALE (0.1f / 8.0f)   // 0.1 / sqrt(64)

// Scratch (allocation-free rule: __device__ globals)
__device__ float g_qkv[(size_t)Mm * N3];   // [4096, 3072] (tf32-rounded)
__device__ float g_y[(size_t)Mm * Cc];     // [4096, 1024] (tf32-rounded)
__device__ float g_xr[(size_t)Mm * Cc];    // x, tf32-rounded
__device__ float g_war[(size_t)Cc * N3];   // w_attn, tf32-rounded
__device__ float g_wpr[(size_t)Cc * Cc];   // w_proj, tf32-rounded

__device__ __forceinline__ unsigned f2tf32(float x) {
    unsigned r;
    asm("cvt.rna.tf32.f32 %0, %1;" : "=r"(r) : "f"(x));
    return r;
}
__device__ __forceinline__ float tf32r(float x) {
    return __uint_as_float(f2tf32(x));
}

#define MMA_TF32(d, a, b0, b1)                                              \
    asm volatile(                                                           \
        "mma.sync.aligned.m16n8k8.row.col.f32.tf32.tf32.f32 "               \
        "{%0,%1,%2,%3}, {%4,%5,%6,%7}, {%8,%9}, {%0,%1,%2,%3};"             \
        : "+f"(d[0]), "+f"(d[1]), "+f"(d[2]), "+f"(d[3])                    \
        : "r"(a[0]), "r"(a[1]), "r"(a[2]), "r"(a[3]), "r"(b0), "r"(b1))

__device__ __forceinline__ void cp16(uint32_t s, const void* g) {
    asm volatile("cp.async.cg.shared.global [%0], [%1], 16;"
                 :: "r"(s), "l"(g));
}
#define CP_COMMIT() asm volatile("cp.async.commit_group;" ::: "memory")
#define CP_WAIT(n)  asm volatile("cp.async.wait_group %0;" :: "n"(n) : "memory")

// ---------------------------------------------------------------------------
// Elementwise tf32 rounding (float4 grid-stride)
// ---------------------------------------------------------------------------
__global__ void cvt_tf32_kernel(const float* __restrict__ in,
                                float* __restrict__ out, int n4)
{
    for (int i = blockIdx.x * blockDim.x + threadIdx.x; i < n4;
         i += gridDim.x * blockDim.x) {
        float4 v = ((const float4*)in)[i];
        v.x = tf32r(v.x); v.y = tf32r(v.y);
        v.z = tf32r(v.z); v.w = tf32r(v.w);
        ((float4*)out)[i] = v;
    }
}

// ---------------------------------------------------------------------------
// TF32 tensor-core GEMM + bias, cp.async 3-stage pipeline, BK=32.
// CTA tile 128x256, 8 warps (2x4), warp tile 64x64, m16n8k8.
// A stride 36 -> A-frag banks 4*lg+lk (conflict-free).
// B stride 264 -> B-frag banks 8*lk+lg (conflict-free).
// One __syncthreads per BK=32 iteration. 1 CTA/SM (153KB smem, 128 acc regs).
// ---------------------------------------------------------------------------
#define GSTAGE 3
#define A_ST 36
#define B_ST 264
#define SMEM_GEMM (GSTAGE * (128 * A_ST + 32 * B_ST) * 4)

__global__ __launch_bounds__(256, 1) void gemm_tf32_bias_kernel(
    const float* __restrict__ A, const float* __restrict__ Bm,
    const float* __restrict__ bias, float* __restrict__ C,
    int M, int N, int K, int round_out)
{
    extern __shared__ float sm[];
    float (*As)[128][A_ST] = (float(*)[128][A_ST])sm;
    float (*Bs)[32][B_ST]  = (float(*)[32][B_ST])(sm + GSTAGE * 128 * A_ST);

    const int tid  = threadIdx.x;
    const int lane = tid & 31;
    const int warp = tid >> 5;
    const int bm = blockIdx.y * 128;
    const int bn = blockIdx.x * 256;
    const int wm = (warp >> 2) * 64;   // 0 or 64
    const int wn = (warp & 3) * 64;    // 0,64,128,192

    float acc[4][8][4];
#pragma unroll
    for (int i = 0; i < 4; i++)
#pragma unroll
        for (int j = 0; j < 8; j++)
#pragma unroll
            for (int r = 0; r < 4; r++) acc[i][j][r] = 0.f;

    // cp.async indexing: A tile 128x32, B tile 32x256
    const int a_row = tid >> 3;           // 0..31  (+ i*32)
    const int a_c   = (tid & 7) * 4;      // float col 0..28
    const int b_row = tid >> 5;           // 0..7   (+ i*8)
    const int b_c   = (tid & 31) * 4;     // float col 0..124 (+ j*128)

    const int KT = K >> 5;

    auto issue = [&](int kt) {
        int s = kt % GSTAGE;
        int k0 = kt << 5;
#pragma unroll
        for (int i = 0; i < 4; i++) {
            int ar = a_row + i * 32;
            cp16((uint32_t)__cvta_generic_to_shared(&As[s][ar][a_c]),
                 A + (size_t)(bm + ar) * K + k0 + a_c);
        }
#pragma unroll
        for (int i = 0; i < 4; i++) {
            int br = b_row + i * 8;
#pragma unroll
            for (int j = 0; j < 2; j++) {
                int bc = b_c + j * 128;
                cp16((uint32_t)__cvta_generic_to_shared(&Bs[s][br][bc]),
                     Bm + (size_t)(k0 + br) * N + bn + bc);
            }
        }
        CP_COMMIT();
    };

    issue(0);
    issue(1);

    const int lg = lane >> 2;
    const int lk = lane & 3;

    for (int kt = 0; kt < KT; kt++) {
        if (kt + 1 < KT) { CP_WAIT(1); } else { CP_WAIT(0); }
        __syncthreads();
        if (kt + 2 < KT) issue(kt + 2);

        int s = kt % GSTAGE;
        float (*Asb)[A_ST] = As[s];
        float (*Bsb)[B_ST] = Bs[s];

#pragma unroll
        for (int ks = 0; ks < 4; ks++) {
            int kb = ks * 8;
            unsigned af[4][4];
#pragma unroll
            for (int mi = 0; mi < 4; mi++) {
                int r = wm + mi * 16 + lg;
                af[mi][0] = __float_as_uint(Asb[r][kb + lk]);
                af[mi][1] = __float_as_uint(Asb[r + 8][kb + lk]);
                af[mi][2] = __float_as_uint(Asb[r][kb + lk + 4]);
                af[mi][3] = __float_as_uint(Asb[r + 8][kb + lk + 4]);
            }
#pragma unroll
            for (int ni = 0; ni < 8; ni++) {
                int cn = wn + ni * 8 + lg;
                unsigned b0 = __float_as_uint(Bsb[kb + lk][cn]);
                unsigned b1 = __float_as_uint(Bsb[kb + lk + 4][cn]);
#pragma unroll
                for (int mi = 0; mi < 4; mi++)
                    MMA_TF32(acc[mi][ni], af[mi], b0, b1);
            }
        }
    }

#pragma unroll
    for (int mi = 0; mi < 4; mi++) {
#pragma unroll
        for (int ni = 0; ni < 8; ni++) {
            int row = bm + wm + mi * 16 + lg;
            int col = bn + wn + ni * 8 + (lk << 1);
            float b0 = bias[col], b1 = bias[col + 1];
            float2 v0 = make_float2(acc[mi][ni][0] + b0, acc[mi][ni][1] + b1);
            float2 v1 = make_float2(acc[mi][ni][2] + b0, acc[mi][ni][3] + b1);
            if (round_out) {
                v0.x = tf32r(v0.x); v0.y = tf32r(v0.y);
                v1.x = tf32r(v1.x); v1.y = tf32r(v1.y);
            }
            *(float2*)(C + (size_t)row * N + col) = v0;
            *(float2*)(C + (size_t)(row + 8) * N + col) = v1;
        }
    }
}

// ---------------------------------------------------------------------------
// Tensor-core causal flash attention (tf32 mma), cp.async double-buffered K/V.
// (unchanged from round 6 — passing)
// ---------------------------------------------------------------------------
#define KS_STRIDE 68
#define VS_STRIDE 72
#define PS_STRIDE 68
#define SMEM_ATTN ((2 * 64 * (KS_STRIDE + VS_STRIDE) + 128 * PS_STRIDE) * 4)

__global__ __launch_bounds__(256, 2) void attn_tc_kernel(
    const float* __restrict__ qkv, float* __restrict__ y)
{
    extern __shared__ float sma[];
    float (*Ks)[64][KS_STRIDE] = (float(*)[64][KS_STRIDE])sma;
    float (*Vs)[64][VS_STRIDE] =
        (float(*)[64][VS_STRIDE])(sma + 2 * 64 * KS_STRIDE);
    float (*Ps)[PS_STRIDE] =
        (float(*)[PS_STRIDE])(sma + 2 * 64 * (KS_STRIDE + VS_STRIDE));

    const int qb = (gridDim.x - 1) - blockIdx.x;
    const int bh = blockIdx.y;
    const int b = bh >> 4;
    const int h = bh & 15;
    const int tid = threadIdx.x;
    const int lane = tid & 31;
    const int warp = tid >> 5;
    const int lg = lane >> 2;
    const int lk = lane & 3;
    const int wrow = warp * 16;

    const float* base  = qkv + (size_t)b * Tt * N3;
    const float* kbase = base + Cc + h * Dd;

    const int ldr = tid >> 2;
    const int ldc = (tid & 3) * 4;

    auto issue = [&](int kb) {
        int buf = kb & 1;
#pragma unroll
        for (int i = 0; i < 4; i++) {
            int c = ldc + i * 16;
            const float* kr = kbase + (size_t)(kb * 64 + ldr) * N3 + c;
            cp16((uint32_t)__cvta_generic_to_shared(&Ks[buf][ldr][c]), kr);
            cp16((uint32_t)__cvta_generic_to_shared(&Vs[buf][ldr][c]), kr + Cc);
        }
        CP_COMMIT();
    };

    issue(0);

    unsigned qf[8][4];
    {
        const float* q0 = base + (size_t)(qb * 128 + wrow + lg) * N3 + h * Dd;
        const float* q1 = q0 + 8 * (size_t)N3;
#pragma unroll
        for (int ks = 0; ks < 8; ks++) {
            qf[ks][0] = f2tf32(q0[ks * 8 + lk] * ATT_SCALE);
            qf[ks][1] = f2tf32(q1[ks * 8 + lk] * ATT_SCALE);
            qf[ks][2] = f2tf32(q0[ks * 8 + lk + 4] * ATT_SCALE);
            qf[ks][3] = f2tf32(q1[ks * 8 + lk + 4] * ATT_SCALE);
        }
    }

    float o[8][4];
#pragma unroll
    for (int nt = 0; nt < 8; nt++)
#pragma unroll
        for (int r = 0; r < 4; r++) o[nt][r] = 0.f;
    float m0 = -1e30f, m1 = -1e30f, l0 = 0.f, l1 = 0.f;

    const int ntiles = 2 * qb + 2;
    const int q0g = qb * 128 + wrow + lg;
    const int q1g = q0g + 8;

#pragma unroll 1
    for (int kb = 0; kb < ntiles; kb++) {
        CP_WAIT(0);
        __syncthreads();
        if (kb + 1 < ntiles) issue(kb + 1);

        const int buf = kb & 1;
        float (*Kb)[KS_STRIDE] = Ks[buf];
        float (*Vb)[VS_STRIDE] = Vs[buf];

        float sa[8][4];
#pragma unroll
        for (int nt = 0; nt < 8; nt++)
#pragma unroll
            for (int r = 0; r < 4; r++) sa[nt][r] = 0.f;

#pragma unroll
        for (int ks = 0; ks < 8; ks++) {
#pragma unroll
            for (int nt = 0; nt < 8; nt++) {
                unsigned b0 = __float_as_uint(Kb[nt * 8 + lg][ks * 8 + lk]);
                unsigned b1 = __float_as_uint(Kb[nt * 8 + lg][ks * 8 + lk + 4]);
                MMA_TF32(sa[nt], qf[ks], b0, b1);
            }
        }

        if (kb * 64 + 63 > qb * 128 + wrow) {
#pragma unroll
            for (int nt = 0; nt < 8; nt++) {
                int kg = kb * 64 + nt * 8 + 2 * lk;
                sa[nt][0] = (kg     <= q0g) ? sa[nt][0] : -1e30f;
                sa[nt][1] = (kg + 1 <= q0g) ? sa[nt][1] : -1e30f;
                sa[nt][2] = (kg     <= q1g) ? sa[nt][2] : -1e30f;
                sa[nt][3] = (kg + 1 <= q1g) ? sa[nt][3] : -1e30f;
            }
        }

        float mt0 = -1e30f, mt1 = -1e30f;
#pragma unroll
        for (int nt = 0; nt < 8; nt++) {
            mt0 = fmaxf(mt0, fmaxf(sa[nt][0], sa[nt][1]));
            mt1 = fmaxf(mt1, fmaxf(sa[nt][2], sa[nt][3]));
        }
        mt0 = fmaxf(mt0, __shfl_xor_sync(0xffffffff, mt0, 1));
        mt0 = fmaxf(mt0, __shfl_xor_sync(0xffffffff, mt0, 2));
        mt1 = fmaxf(mt1, __shfl_xor_sync(0xffffffff, mt1, 1));
        mt1 = fmaxf(mt1, __shfl_xor_sync(0xffffffff, mt1, 2));

        float mn0 = fmaxf(m0, mt0), mn1 = fmaxf(m1, mt1);
        float sc0 = __expf(m0 - mn0), sc1 = __expf(m1 - mn1);
        m0 = mn0; m1 = mn1;

#pragma unroll
        for (int nt = 0; nt < 8; nt++) {
            o[nt][0] *= sc0; o[nt][1] *= sc0;
            o[nt][2] *= sc1; o[nt][3] *= sc1;
        }

        float s0 = 0.f, s1 = 0.f;
#pragma unroll
        for (int nt = 0; nt < 8; nt++) {
            float p0 = __expf(sa[nt][0] - mn0);
            float p1 = __expf(sa[nt][1] - mn0);
            float p2 = __expf(sa[nt][2] - mn1);
            float p3 = __expf(sa[nt][3] - mn1);
            s0 += p0 + p1; s1 += p2 + p3;
            float2 v0, v1;
            v0.x = tf32r(p0); v0.y = tf32r(p1);
            v1.x = tf32r(p2); v1.y = tf32r(p3);
            *(float2*)(&Ps[wrow + lg][nt * 8 + 2 * lk]) = v0;
            *(float2*)(&Ps[wrow + 8 + lg][nt * 8 + 2 * lk]) = v1;
        }
        s0 += __shfl_xor_sync(0xffffffff, s0, 1);
        s0 += __shfl_xor_sync(0xffffffff, s0, 2);
        s1 += __shfl_xor_sync(0xffffffff, s1, 1);
        s1 += __shfl_xor_sync(0xffffffff, s1, 2);
        l0 = l0 * sc0 + s0;
        l1 = l1 * sc1 + s1;

        __syncwarp();

#pragma unroll
        for (int ks = 0; ks < 8; ks++) {
            unsigned af[4];
            af[0] = __float_as_uint(Ps[wrow + lg][ks * 8 + lk]);
            af[1] = __float_as_uint(Ps[wrow + 8 + lg][ks * 8 + lk]);
            af[2] = __float_as_uint(Ps[wrow + lg][ks * 8 + lk + 4]);
            af[3] = __float_as_uint(Ps[wrow + 8 + lg][ks * 8 + lk + 4]);
#pragma unroll
            for (int nt = 0; nt < 8; nt++) {
                unsigned b0 = __float_as_uint(Vb[ks * 8 + lk][nt * 8 + lg]);
                unsigned b1 = __float_as_uint(Vb[ks * 8 + lk + 4][nt * 8 + lg]);
                MMA_TF32(o[nt], af, b0, b1);
            }
        }
    }

    float i0 = 1.f / l0, i1 = 1.f / l1;
    float* y0 = y + ((size_t)b * Tt + qb * 128 + wrow + lg) * Cc + h * Dd;
    float* y1 = y0 + 8 * (size_t)Cc;
#pragma unroll
    for (int nt = 0; nt < 8; nt++) {
        float2 w0, w1;
        w0.x = tf32r(o[nt][0] * i0);
        w0.y = tf32r(o[nt][1] * i0);
        w1.x = tf32r(o[nt][2] * i1);
        w1.y = tf32r(o[nt][3] * i1);
        *(float2*)(y0 + nt * 8 + 2 * lk) = w0;
        *(float2*)(y1 + nt * 8 + 2 * lk) = w1;
    }
}

// ---------------------------------------------------------------------------
extern "C" void kernel_launch(void* const* d_in, const int* in_sizes, int n_in,
                              void* d_out, int out_size)
{
    const float* x      = (const float*)d_in[0];
    const float* w_attn = (const float*)d_in[1];
    const float* b_attn = (const float*)d_in[2];
    const float* w_proj = (const float*)d_in[3];
    const float* b_proj = (const float*)d_in[4];
    float* out = (float*)d_out;

    void *qkv_p, *y_p, *xr_p, *war_p, *wpr_p;
    cudaGetSymbolAddress(&qkv_p, g_qkv);
    cudaGetSymbolAddress(&y_p, g_y);
    cudaGetSymbolAddress(&xr_p, g_xr);
    cudaGetSymbolAddress(&war_p, g_war);
    cudaGetSymbolAddress(&wpr_p, g_wpr);
    float* qkv = (float*)qkv_p;
    float* y   = (float*)y_p;
    float* xr  = (float*)xr_p;
    float* war = (float*)war_p;
    float* wpr = (float*)wpr_p;

    static bool attr_set = false;
    if (!attr_set) {
        cudaFuncSetAttribute(attn_tc_kernel,
                             cudaFuncAttributeMaxDynamicSharedMemorySize,
                             SMEM_ATTN);
        cudaFuncSetAttribute(gemm_tf32_bias_kernel,
                             cudaFuncAttributeMaxDynamicSharedMemorySize,
                             SMEM_GEMM);
        attr_set = true;
    }

    // 0) pre-round GEMM inputs to tf32
    cvt_tf32_kernel<<<1024, 256>>>(x, xr, Mm * Cc / 4);
    cvt_tf32_kernel<<<1024, 256>>>(w_attn, war, Cc * N3 / 4);
    cvt_tf32_kernel<<<1024, 256>>>(w_proj, wpr, Cc * Cc / 4);

    // 1) qkv = xr @ war + b_attn  (output rounded to tf32)
    {
        dim3 grid(N3 / 256, Mm / 128);
        gemm_tf32_bias_kernel<<<grid, 256, SMEM_GEMM>>>(
            xr, war, b_attn, qkv, Mm, N3, Cc, 1);
    }
    // 2) causal attention -> y (rounded to tf32)
    {
        dim3 grid(Tt / 128, Bt * Hh);
        attn_tc_kernel<<<grid, 256, SMEM_ATTN>>>(qkv, y);
    }
    // 3) out = y @ wpr + b_proj  (full fp32 output)
    {
        dim3 grid(Cc / 256, Mm / 128);
        gemm_tf32_bias_kernel<<<grid, 256, SMEM_GEMM>>>(
            y, wpr, b_proj, out, Mm, Cc, Cc, 0);
    }
}